// round 6
// baseline (speedup 1.0000x reference)
#include <cuda_runtime.h>
#include <cuda_fp16.h>
#include <math.h>
#include <stdint.h>

#define DIMV   64
#define NG     512
#define NNODES 20000
#define NEDGES 60000
#define NFEAT  11
#define EHID   128
#define WE_COLS 4096   // DIM*DIM

// ---------------- scratch ----------------
__device__ __half g_We_h[(size_t)NEDGES * WE_COLS];   // 491 MB
__device__ __half g_hedge_h[NEDGES * EHID];
__device__ __half g_nn2w_h[WE_COLS * EHID];
__device__ __half g_nodew_h[448 * 64];                // [root(64) | Wih(192) | Whh(192)]
__device__ float g_h[NNODES * DIMV];
__device__ float g_agg[NNODES * DIMV];
__device__ float g_invdeg[NNODES];
__device__ int   g_degi[NNODES];
__device__ int   g_cnt[NG];
__device__ int   g_gstart[NG + 1];
__device__ float g_ebuf[NNODES];
__device__ float g_wihT[128 * 256];
__device__ float g_whhT[64 * 256];
__device__ float g_lin1T[128 * 64];

// ---------------- lin0 GEMM (fp32) + agg zeroing fused in epilogue ----------------
#define BM 64
#define BN 64
#define BKK 16

__global__ void gemm_kernel(const float* __restrict__ A, const float* __restrict__ W,
                            const float* __restrict__ bias,
                            float* __restrict__ C, float* __restrict__ zbuf,
                            int M, int Nc, int K, int do_relu)
{
    __shared__ float As[BKK][BM];
    __shared__ float Ws[BKK][BN];

    const int bm = blockIdx.y * BM;
    const int bn = blockIdx.x * BN;
    const int tid = threadIdx.x;
    const int tm = (tid / 16) * 4;
    const int tn = (tid % 16) * 4;

    float acc[4][4];
#pragma unroll
    for (int i = 0; i < 4; i++)
#pragma unroll
        for (int j = 0; j < 4; j++) acc[i][j] = 0.f;

    for (int k0 = 0; k0 < K; k0 += BKK) {
#pragma unroll
        for (int r = 0; r < 4; r++) {
            int idx = tid + r * 256;
            int mm = idx / BKK, kk = idx % BKK;
            int gm = bm + mm, gk = k0 + kk;
            float v = 0.f;
            if (gm < M && gk < K) v = A[(size_t)gm * K + gk];
            As[kk][mm] = v;
        }
#pragma unroll
        for (int r = 0; r < 4; r++) {
            int idx = tid + r * 256;
            int nn = idx / BKK, kk = idx % BKK;
            int gn = bn + nn, gk = k0 + kk;
            float v = 0.f;
            if (gn < Nc && gk < K) v = W[(size_t)gn * K + gk];
            Ws[kk][nn] = v;
        }
        __syncthreads();

#pragma unroll
        for (int kk = 0; kk < BKK; kk++) {
            float a0 = As[kk][tm + 0], a1 = As[kk][tm + 1], a2 = As[kk][tm + 2], a3 = As[kk][tm + 3];
            float b0 = Ws[kk][tn + 0], b1 = Ws[kk][tn + 1], b2 = Ws[kk][tn + 2], b3 = Ws[kk][tn + 3];
            acc[0][0] += a0 * b0; acc[0][1] += a0 * b1; acc[0][2] += a0 * b2; acc[0][3] += a0 * b3;
            acc[1][0] += a1 * b0; acc[1][1] += a1 * b1; acc[1][2] += a1 * b2; acc[1][3] += a1 * b3;
            acc[2][0] += a2 * b0; acc[2][1] += a2 * b1; acc[2][2] += a2 * b2; acc[2][3] += a2 * b3;
            acc[3][0] += a3 * b0; acc[3][1] += a3 * b1; acc[3][2] += a3 * b2; acc[3][3] += a3 * b3;
        }
        __syncthreads();
    }

#pragma unroll
    for (int i = 0; i < 4; i++) {
        int gm = bm + tm + i;
        if (gm >= M) continue;
#pragma unroll
        for (int j = 0; j < 4; j++) {
            int gn = bn + tn + j;
            if (gn >= Nc) continue;
            float v = acc[i][j] + bias[gn];
            if (do_relu) v = fmaxf(v, 0.f);
            C[(size_t)gm * Nc + gn] = v;
            if (zbuf) zbuf[(size_t)gm * Nc + gn] = 0.f;
        }
    }
}

// ---------------- fused prep: f2h(nn2_w) + combined node weights + transposes ----------------
__global__ void prep_kernel(const float* __restrict__ nn2_w,
                            const float* __restrict__ root_w,
                            const float* __restrict__ wih, const float* __restrict__ whh,
                            const float* __restrict__ lstm_w_ih, const float* __restrict__ lstm_w_hh,
                            const float* __restrict__ lin1_w)
{
    int i = blockIdx.x * blockDim.x + threadIdx.x;
    if (i < WE_COLS * EHID) g_nn2w_h[i] = __float2half(nn2_w[i]);
    if (i < 448 * 64) {
        int row = i >> 6, k = i & 63;
        float v;
        if (row < 64)       v = root_w[row * 64 + k];
        else if (row < 256) v = wih[(row - 64) * 64 + k];
        else                v = whh[(row - 256) * 64 + k];
        g_nodew_h[i] = __float2half(v);
    }
    if (i < 256 * 128) { int r = i / 128, k = i % 128; g_wihT[k * 256 + r] = lstm_w_ih[i]; }
    if (i < 256 * 64)  { int r = i / 64,  k = i % 64;  g_whhT[k * 256 + r] = lstm_w_hh[i]; }
    if (i < 64 * 128)  { int r = i / 128, k = i % 128; g_lin1T[k * 64 + r] = lin1_w[i]; }
}

// ---------------- edge MLP layer 1 ----------------
__global__ void edge_mlp1_kernel(const float* __restrict__ ea,
                                 const float* __restrict__ nn1_w, const float* __restrict__ nn1_b,
                                 int E)
{
    int idx = blockIdx.x * blockDim.x + threadIdx.x;
    if (idx >= E * EHID) return;
    int e = idx / EHID, j = idx % EHID;
    float acc = nn1_b[j];
    const float* w = nn1_w + j * 5;
    const float* a = ea + e * 5;
#pragma unroll
    for (int k = 0; k < 5; k++) acc += a[k] * __ldg(&w[k]);
    g_hedge_h[idx] = __float2half(fmaxf(acc, 0.f));
}

// ---------------- mma helper ----------------
__device__ __forceinline__ void mma16816(float c[4], const uint32_t a[4], uint32_t b0, uint32_t b1)
{
    asm volatile(
        "mma.sync.aligned.m16n8k16.row.col.f32.f16.f16.f32 "
        "{%0,%1,%2,%3}, {%4,%5,%6,%7}, {%8,%9}, {%0,%1,%2,%3};\n"
        : "+f"(c[0]), "+f"(c[1]), "+f"(c[2]), "+f"(c[3])
        : "r"(a[0]), "r"(a[1]), "r"(a[2]), "r"(a[3]), "r"(b0), "r"(b1));
}

// ---------------- big GEMM (R4 version: 128x128 block, 2 CTA/SM) ----------------
#define WG_PAD 8
#define WG_LDK (EHID + WG_PAD)

__global__ void __launch_bounds__(256) we_gemm_kernel(
    const __half* __restrict__ A, const __half* __restrict__ B,
    const float* __restrict__ bias, __half* __restrict__ C, int M)
{
    extern __shared__ __half smemh[];
    __half (*As)[WG_LDK] = (__half (*)[WG_LDK])smemh;
    __half (*Bs)[WG_LDK] = (__half (*)[WG_LDK])(smemh + 128 * WG_LDK);

    const int bm = blockIdx.y * 128;
    const int bn = blockIdx.x * 128;
    const int tid = threadIdx.x;
    const int warp = tid >> 5, lane = tid & 31;
    const int wm = (warp & 1) * 64;
    const int wn = (warp >> 1) * 32;

#pragma unroll
    for (int i = 0; i < 8; i++) {
        int idx = tid + i * 256;
        int row = idx >> 4, u = idx & 15;
        int gm = bm + row;
        uint32_t dst = (uint32_t)__cvta_generic_to_shared(&As[row][u * 8]);
        const void* src = A + (size_t)gm * EHID + u * 8;
        int sz = (gm < M) ? 16 : 0;
        asm volatile("cp.async.ca.shared.global [%0], [%1], 16, %2;\n"
                     :: "r"(dst), "l"(src), "r"(sz));
    }
#pragma unroll
    for (int i = 0; i < 8; i++) {
        int idx = tid + i * 256;
        int row = idx >> 4, u = idx & 15;
        uint32_t dst = (uint32_t)__cvta_generic_to_shared(&Bs[row][u * 8]);
        const void* src = B + (size_t)(bn + row) * EHID + u * 8;
        asm volatile("cp.async.ca.shared.global [%0], [%1], 16;\n"
                     :: "r"(dst), "l"(src));
    }
    asm volatile("cp.async.commit_group;\n" ::: "memory");
    asm volatile("cp.async.wait_group 0;\n" ::: "memory");
    __syncthreads();

    float c[4][4][4];
#pragma unroll
    for (int mt = 0; mt < 4; mt++)
#pragma unroll
        for (int nt = 0; nt < 4; nt++)
#pragma unroll
            for (int i = 0; i < 4; i++) c[mt][nt][i] = 0.f;

    const int g = lane >> 3, r = lane & 7;

#pragma unroll
    for (int k0 = 0; k0 < EHID; k0 += 16) {
        uint32_t af[4][4];
#pragma unroll
        for (int mt = 0; mt < 4; mt++) {
            uint32_t addr = (uint32_t)__cvta_generic_to_shared(
                &As[wm + mt * 16 + r + (g & 1) * 8][k0 + (g >> 1) * 8]);
            asm volatile("ldmatrix.sync.aligned.m8n8.x4.shared.b16 {%0,%1,%2,%3}, [%4];"
                         : "=r"(af[mt][0]), "=r"(af[mt][1]), "=r"(af[mt][2]), "=r"(af[mt][3])
                         : "r"(addr));
        }
        uint32_t bf[4][2];
#pragma unroll
        for (int p = 0; p < 2; p++) {
            uint32_t addr = (uint32_t)__cvta_generic_to_shared(
                &Bs[wn + p * 16 + r + (g >> 1) * 8][k0 + (g & 1) * 8]);
            uint32_t b0, b1, b2, b3;
            asm volatile("ldmatrix.sync.aligned.m8n8.x4.shared.b16 {%0,%1,%2,%3}, [%4];"
                         : "=r"(b0), "=r"(b1), "=r"(b2), "=r"(b3) : "r"(addr));
            bf[2 * p][0] = b0; bf[2 * p][1] = b1;
            bf[2 * p + 1][0] = b2; bf[2 * p + 1][1] = b3;
        }
#pragma unroll
        for (int mt = 0; mt < 4; mt++)
#pragma unroll
            for (int nt = 0; nt < 4; nt++)
                mma16816(c[mt][nt], af[mt], bf[nt][0], bf[nt][1]);
    }

#pragma unroll
    for (int mt = 0; mt < 4; mt++) {
        int row0 = bm + wm + mt * 16 + (lane >> 2);
#pragma unroll
        for (int nt = 0; nt < 4; nt++) {
            int gn = bn + wn + nt * 8 + 2 * (lane & 3);
            float b0 = bias[gn], b1 = bias[gn + 1];
            if (row0 < M) {
                __half2 h = __floats2half2_rn(c[mt][nt][0] + b0, c[mt][nt][1] + b1);
                *(__half2*)(C + (size_t)row0 * WE_COLS + gn) = h;
            }
            if (row0 + 8 < M) {
                __half2 h = __floats2half2_rn(c[mt][nt][2] + b0, c[mt][nt][3] + b1);
                *(__half2*)(C + (size_t)(row0 + 8) * WE_COLS + gn) = h;
            }
        }
    }
}

// ---------------- fused node update (R4, validated) + agg re-zeroing ----------------
#define NU_LD 72

__device__ __forceinline__ void nu_lda(const __half (*sh)[NU_LD], int wm, int k0, int lane, uint32_t af[2][4])
{
    const int g = lane >> 3, r = lane & 7;
#pragma unroll
    for (int mt = 0; mt < 2; mt++) {
        uint32_t addr = (uint32_t)__cvta_generic_to_shared(
            &sh[wm + mt * 16 + r + (g & 1) * 8][k0 + (g >> 1) * 8]);
        asm volatile("ldmatrix.sync.aligned.m8n8.x4.shared.b16 {%0,%1,%2,%3}, [%4];"
                     : "=r"(af[mt][0]), "=r"(af[mt][1]), "=r"(af[mt][2]), "=r"(af[mt][3])
                     : "r"(addr));
    }
}

__device__ __forceinline__ void nu_ldb(const __half (*shW)[NU_LD], int rowbase, int wn, int k0, int lane,
                                       uint32_t bf[4][2])
{
    const int g = lane >> 3, r = lane & 7;
#pragma unroll
    for (int p = 0; p < 2; p++) {
        uint32_t addr = (uint32_t)__cvta_generic_to_shared(
            &shW[rowbase + wn + p * 16 + r + (g >> 1) * 8][k0 + (g & 1) * 8]);
        uint32_t b0, b1, b2, b3;
        asm volatile("ldmatrix.sync.aligned.m8n8.x4.shared.b16 {%0,%1,%2,%3}, [%4];"
                     : "=r"(b0), "=r"(b1), "=r"(b2), "=r"(b3) : "r"(addr));
        bf[2 * p][0] = b0; bf[2 * p][1] = b1;
        bf[2 * p + 1][0] = b2; bf[2 * p + 1][1] = b3;
    }
}

__device__ __forceinline__ void nu_mma(const __half (*shA)[NU_LD], const __half (*shW)[NU_LD],
                                       int rowbase, int wm, int wn, int lane, float c[2][4][4])
{
#pragma unroll
    for (int k0 = 0; k0 < 64; k0 += 16) {
        uint32_t af[2][4];
        nu_lda(shA, wm, k0, lane, af);
        uint32_t bf[4][2];
        nu_ldb(shW, rowbase, wn, k0, lane, bf);
#pragma unroll
        for (int mt = 0; mt < 2; mt++)
#pragma unroll
            for (int nt = 0; nt < 4; nt++)
                mma16816(c[mt][nt], af[mt], bf[nt][0], bf[nt][1]);
    }
}

__device__ __forceinline__ float sigmoidf_(float x) { return 1.f / (1.f + expf(-x)); }

__global__ void __launch_bounds__(256) node_update_kernel(
    const float* __restrict__ conv_b, const float* __restrict__ b_ih, const float* __restrict__ b_hh,
    int N)
{
    extern __shared__ __half sm_[];
    __half (*shW)[NU_LD] = (__half (*)[NU_LD])sm_;
    __half (*shH)[NU_LD] = (__half (*)[NU_LD])(sm_ + 448 * NU_LD);
    __half (*shM)[NU_LD] = (__half (*)[NU_LD])(sm_ + (448 + 128) * NU_LD);

    const int bm = blockIdx.x * 128;
    const int tid = threadIdx.x;
    const int warp = tid >> 5, lane = tid & 31;
    const int wm = (warp & 3) * 32;
    const int wn = (warp >> 2) * 32;

#pragma unroll
    for (int i = 0; i < 14; i++) {
        int idx = tid + i * 256;
        int row = idx >> 3, u = idx & 7;
        uint32_t dst = (uint32_t)__cvta_generic_to_shared(&shW[row][u * 8]);
        const void* src = g_nodew_h + (size_t)row * 64 + u * 8;
        asm volatile("cp.async.ca.shared.global [%0], [%1], 16;\n" :: "r"(dst), "l"(src));
    }
    asm volatile("cp.async.commit_group;\n" ::: "memory");

#pragma unroll
    for (int i = 0; i < 8; i++) {
        int idx = tid + i * 256;
        int row = idx >> 4, u = idx & 15;
        int grow = bm + row;
        float4 v = make_float4(0.f, 0.f, 0.f, 0.f);
        if (grow < N) v = *(const float4*)(g_h + (size_t)grow * DIMV + u * 4);
        *(__half2*)(&shH[row][u * 4])     = __floats2half2_rn(v.x, v.y);
        *(__half2*)(&shH[row][u * 4 + 2]) = __floats2half2_rn(v.z, v.w);
    }
    asm volatile("cp.async.wait_group 0;\n" ::: "memory");
    __syncthreads();

    // stage1: m = relu(agg*invdeg + h@root^T + conv_b); re-zero agg after consuming it
    {
        float c[2][4][4];
#pragma unroll
        for (int mt = 0; mt < 2; mt++)
#pragma unroll
            for (int nt = 0; nt < 4; nt++)
#pragma unroll
                for (int i = 0; i < 4; i++) c[mt][nt][i] = 0.f;
        nu_mma(shH, shW, 0, wm, wn, lane, c);

#pragma unroll
        for (int mt = 0; mt < 2; mt++) {
            int lrow0 = wm + mt * 16 + (lane >> 2);
#pragma unroll
            for (int nt = 0; nt < 4; nt++) {
                int col = wn + nt * 8 + 2 * (lane & 3);
                float cb0 = conv_b[col], cb1 = conv_b[col + 1];
#pragma unroll
                for (int hrow = 0; hrow < 2; hrow++) {
                    int lrow = lrow0 + hrow * 8;
                    int grow = bm + lrow;
                    float a0 = 0.f, a1 = 0.f;
                    if (grow < N) {
                        float id = g_invdeg[grow];
                        float2 ag = *(const float2*)(g_agg + (size_t)grow * DIMV + col);
                        a0 = ag.x * id; a1 = ag.y * id;
                        *(float2*)(g_agg + (size_t)grow * DIMV + col) = make_float2(0.f, 0.f);
                    }
                    float m0 = fmaxf(c[mt][nt][2 * hrow]     + a0 + cb0, 0.f);
                    float m1 = fmaxf(c[mt][nt][2 * hrow + 1] + a1 + cb1, 0.f);
                    *(__half2*)(&shM[lrow][col]) = __floats2half2_rn(m0, m1);
                }
            }
        }
    }
    __syncthreads();

    // gate r
    float rfr[2][4][4];
#pragma unroll
    for (int mt = 0; mt < 2; mt++)
#pragma unroll
        for (int nt = 0; nt < 4; nt++)
#pragma unroll
            for (int i = 0; i < 4; i++) rfr[mt][nt][i] = 0.f;
    nu_mma(shM, shW, 64, wm, wn, lane, rfr);
    nu_mma(shH, shW, 256, wm, wn, lane, rfr);
#pragma unroll
    for (int mt = 0; mt < 2; mt++)
#pragma unroll
        for (int nt = 0; nt < 4; nt++) {
            int col = wn + nt * 8 + 2 * (lane & 3);
            float bb0 = b_ih[col] + b_hh[col];
            float bb1 = b_ih[col + 1] + b_hh[col + 1];
            rfr[mt][nt][0] = sigmoidf_(rfr[mt][nt][0] + bb0);
            rfr[mt][nt][1] = sigmoidf_(rfr[mt][nt][1] + bb1);
            rfr[mt][nt][2] = sigmoidf_(rfr[mt][nt][2] + bb0);
            rfr[mt][nt][3] = sigmoidf_(rfr[mt][nt][3] + bb1);
        }

    // gate n
    float nfr[2][4][4];
    {
        float cin[2][4][4], chn[2][4][4];
#pragma unroll
        for (int mt = 0; mt < 2; mt++)
#pragma unroll
            for (int nt = 0; nt < 4; nt++)
#pragma unroll
                for (int i = 0; i < 4; i++) { cin[mt][nt][i] = 0.f; chn[mt][nt][i] = 0.f; }
        nu_mma(shM, shW, 64 + 128, wm, wn, lane, cin);
        nu_mma(shH, shW, 256 + 128, wm, wn, lane, chn);
#pragma unroll
        for (int mt = 0; mt < 2; mt++)
#pragma unroll
            for (int nt = 0; nt < 4; nt++) {
                int col = wn + nt * 8 + 2 * (lane & 3);
                float bi0 = b_ih[128 + col], bi1 = b_ih[128 + col + 1];
                float bh0 = b_hh[128 + col], bh1 = b_hh[128 + col + 1];
                nfr[mt][nt][0] = tanhf(cin[mt][nt][0] + bi0 + rfr[mt][nt][0] * (chn[mt][nt][0] + bh0));
                nfr[mt][nt][1] = tanhf(cin[mt][nt][1] + bi1 + rfr[mt][nt][1] * (chn[mt][nt][1] + bh1));
                nfr[mt][nt][2] = tanhf(cin[mt][nt][2] + bi0 + rfr[mt][nt][2] * (chn[mt][nt][2] + bh0));
                nfr[mt][nt][3] = tanhf(cin[mt][nt][3] + bi1 + rfr[mt][nt][3] * (chn[mt][nt][3] + bh1));
            }
    }

    // gate z + h' = (1-z)*n + z*h_old
    {
        float cz[2][4][4];
#pragma unroll
        for (int mt = 0; mt < 2; mt++)
#pragma unroll
            for (int nt = 0; nt < 4; nt++)
#pragma unroll
                for (int i = 0; i < 4; i++) cz[mt][nt][i] = 0.f;
        nu_mma(shM, shW, 64 + 64, wm, wn, lane, cz);
        nu_mma(shH, shW, 256 + 64, wm, wn, lane, cz);
#pragma unroll
        for (int mt = 0; mt < 2; mt++) {
            int lrow0 = wm + mt * 16 + (lane >> 2);
#pragma unroll
            for (int nt = 0; nt < 4; nt++) {
                int col = wn + nt * 8 + 2 * (lane & 3);
                float bb0 = b_ih[64 + col] + b_hh[64 + col];
                float bb1 = b_ih[64 + col + 1] + b_hh[64 + col + 1];
#pragma unroll
                for (int hrow = 0; hrow < 2; hrow++) {
                    int grow = bm + lrow0 + hrow * 8;
                    if (grow >= N) continue;
                    float z0 = sigmoidf_(cz[mt][nt][2 * hrow]     + bb0);
                    float z1 = sigmoidf_(cz[mt][nt][2 * hrow + 1] + bb1);
                    float2 ho = *(const float2*)(g_h + (size_t)grow * DIMV + col);
                    float2 hn_;
                    hn_.x = (1.f - z0) * nfr[mt][nt][2 * hrow]     + z0 * ho.x;
                    hn_.y = (1.f - z1) * nfr[mt][nt][2 * hrow + 1] + z1 * ho.y;
                    *(float2*)(g_h + (size_t)grow * DIMV + col) = hn_;
                }
            }
        }
    }
}

// ---------------- bookkeeping ----------------
__global__ void count_kernel(const int* __restrict__ ei, const int* __restrict__ batch, int E, int N)
{
    int i = blockIdx.x * blockDim.x + threadIdx.x;
    if (i < E) atomicAdd(&g_degi[ei[E + i]], 1);
    if (i < N) atomicAdd(&g_cnt[batch[i]], 1);
}

__global__ void invdeg_kernel(int N)
{
    int i = blockIdx.x * blockDim.x + threadIdx.x;
    if (i < N) g_invdeg[i] = 1.f / fmaxf((float)g_degi[i], 1.f);
}

__global__ void scan_kernel()
{
    __shared__ int s[NG];
    int t = threadIdx.x;
    s[t] = g_cnt[t];
    __syncthreads();
    for (int off = 1; off < NG; off <<= 1) {
        int v = (t >= off) ? s[t - off] : 0;
        __syncthreads();
        s[t] += v;
        __syncthreads();
    }
    if (t == 0) g_gstart[0] = 0;
    g_gstart[t + 1] = s[t];
}

// ---------------- per-edge message + scatter ----------------
__global__ void msg_kernel(const int* __restrict__ ei, int E)
{
    const int w    = threadIdx.x >> 5;
    const int lane = threadIdx.x & 31;
    const int e    = blockIdx.x * 8 + w;
    __shared__ float s_a[8][DIMV];

    if (e >= E) return;
    int src = ei[e];
    int dst = ei[E + e];
    s_a[w][lane]      = g_h[src * DIMV + lane];
    s_a[w][lane + 32] = g_h[src * DIMV + lane + 32];
    __syncwarp();

    const __half2* __restrict__ wp = (const __half2*)(g_We_h + (size_t)e * WE_COLS) + lane;
    float accx = 0.f, accy = 0.f;
#pragma unroll
    for (int i = 0; i < DIMV; i++) {
        float a = s_a[w][i];
        float2 wv = __half22float2(wp[i * 32]);
        accx = fmaf(a, wv.x, accx);
        accy = fmaf(a, wv.y, accy);
    }
    atomicAdd(&g_agg[dst * DIMV + 2 * lane],     accx);
    atomicAdd(&g_agg[dst * DIMV + 2 * lane + 1], accy);
}

// ---------------- fused Set2Set (3 steps) + readout ----------------
__global__ void __launch_bounds__(128) set2set_kernel(
    const float* __restrict__ b_ih, const float* __restrict__ b_hh,
    const float* __restrict__ lin1_b, const float* __restrict__ lin2_w,
    const float* __restrict__ lin2_b, float* __restrict__ y)
{
    const int b = blockIdx.x, t = threadIdx.x;
    const int s = g_gstart[b], e_end = g_gstart[b + 1];

    __shared__ float qs[2 * DIMV];
    __shared__ float hsv[DIMV];
    __shared__ float csv[DIMV];
    __shared__ float gates[4 * DIMV];
    __shared__ float red[128];

    qs[t] = 0.f;
    if (t < 64) { hsv[t] = 0.f; csv[t] = 0.f; }
    __syncthreads();

    for (int step = 0; step < 3; step++) {
#pragma unroll
        for (int gsel = 0; gsel < 2; gsel++) {
            int gidx = t + gsel * 128;
            float acc = b_ih[gidx] + b_hh[gidx];
#pragma unroll 8
            for (int k = 0; k < 128; k++) acc += qs[k] * g_wihT[k * 256 + gidx];
#pragma unroll 8
            for (int k = 0; k < 64; k++)  acc += hsv[k] * g_whhT[k * 256 + gidx];
            gates[gidx] = acc;
        }
        __syncthreads();
        if (t < 64) {
            float i = sigmoidf_(gates[t]);
            float f = sigmoidf_(gates[64 + t]);
            float g = tanhf(gates[128 + t]);
            float o = sigmoidf_(gates[192 + t]);
            float c = f * csv[t] + i * g;
            csv[t] = c;
            hsv[t] = o * tanhf(c);
        }
        __syncthreads();

        float lmax = -1e30f;
        for (int n = s + t; n < e_end; n += 128) {
            const float* row = g_h + (size_t)n * DIMV;
            float acc = 0.f;
#pragma unroll 8
            for (int i = 0; i < DIMV; i++) acc += row[i] * hsv[i];
            g_ebuf[n] = acc;
            lmax = fmaxf(lmax, acc);
        }
        red[t] = lmax; __syncthreads();
        for (int st = 64; st > 0; st >>= 1) { if (t < st) red[t] = fmaxf(red[t], red[t + st]); __syncthreads(); }
        float gmax = red[0];
        __syncthreads();

        float lsum = 0.f;
        for (int n = s + t; n < e_end; n += 128) {
            float a = expf(g_ebuf[n] - gmax);
            g_ebuf[n] = a;
            lsum += a;
        }
        red[t] = lsum; __syncthreads();
        for (int st = 64; st > 0; st >>= 1) { if (t < st) red[t] += red[t + st]; __syncthreads(); }
        float S = red[0];
        __syncthreads();

        {
            int d = t & 63, half = t >> 6;
            float r = 0.f;
            for (int n = s + half; n < e_end; n += 2)
                r += g_ebuf[n] * g_h[(size_t)n * DIMV + d];
            red[t] = r;
        }
        __syncthreads();
        if (t < 64) {
            float rr = red[t] + red[t + 64];
            qs[t] = hsv[t];
            qs[64 + t] = (e_end > s) ? (rr / S) : 0.f;
        }
        __syncthreads();
    }

    if (t < 64) {
        float acc = lin1_b[t];
#pragma unroll 8
        for (int k = 0; k < 128; k++) acc += qs[k] * g_lin1T[k * 64 + t];
        float z = fmaxf(acc, 0.f);
        red[t] = z * lin2_w[t];
    }
    __syncthreads();
    for (int st = 32; st > 0; st >>= 1) { if (t < st) red[t] += red[t + st]; __syncthreads(); }
    if (t == 0) y[b] = red[0] + lin2_b[0];
}

// ======================================================================================
extern "C" void kernel_launch(void* const* d_in, const int* in_sizes, int n_in,
                              void* d_out, int out_size)
{
    const float* x        = (const float*)d_in[0];
    const int*   ei       = (const int*)  d_in[1];
    const float* ea       = (const float*)d_in[2];
    const int*   batch    = (const int*)  d_in[3];
    const float* lin0_w   = (const float*)d_in[4];
    const float* lin0_b   = (const float*)d_in[5];
    const float* nn1_w    = (const float*)d_in[6];
    const float* nn1_b    = (const float*)d_in[7];
    const float* nn2_w    = (const float*)d_in[8];
    const float* nn2_b    = (const float*)d_in[9];
    const float* root_w   = (const float*)d_in[10];
    const float* conv_b   = (const float*)d_in[11];
    const float* gru_w_ih = (const float*)d_in[12];
    const float* gru_w_hh = (const float*)d_in[13];
    const float* gru_b_ih = (const float*)d_in[14];
    const float* gru_b_hh = (const float*)d_in[15];
    const float* lstm_w_ih= (const float*)d_in[16];
    const float* lstm_w_hh= (const float*)d_in[17];
    const float* lstm_b_ih= (const float*)d_in[18];
    const float* lstm_b_hh= (const float*)d_in[19];
    const float* lin1_w   = (const float*)d_in[20];
    const float* lin1_b   = (const float*)d_in[21];
    const float* lin2_w   = (const float*)d_in[22];
    const float* lin2_b   = (const float*)d_in[23];
    float* y = (float*)d_out;

    const int N = NNODES, E = NEDGES;

    __half *We_h, *hedge_h, *nn2w_h;
    float *h, *agg;
    int *degi, *cnt;
    cudaGetSymbolAddress((void**)&We_h, g_We_h);
    cudaGetSymbolAddress((void**)&hedge_h, g_hedge_h);
    cudaGetSymbolAddress((void**)&nn2w_h, g_nn2w_h);
    cudaGetSymbolAddress((void**)&h, g_h);
    cudaGetSymbolAddress((void**)&agg, g_agg);
    cudaGetSymbolAddress((void**)&degi, g_degi);
    cudaGetSymbolAddress((void**)&cnt, g_cnt);

    const int we_smem = 2 * 128 * WG_LDK * (int)sizeof(__half);  // ~68 KB (2 CTA/SM)
    cudaFuncSetAttribute(we_gemm_kernel, cudaFuncAttributeMaxDynamicSharedMemorySize, we_smem);
    const int nu_smem = (448 + 128 + 128) * NU_LD * (int)sizeof(__half);
    cudaFuncSetAttribute(node_update_kernel, cudaFuncAttributeMaxDynamicSharedMemorySize, nu_smem);

    prep_kernel<<<(WE_COLS * EHID + 255) / 256, 256>>>(nn2_w, root_w, gru_w_ih, gru_w_hh,
                                                       lstm_w_ih, lstm_w_hh, lin1_w);       // 1
    edge_mlp1_kernel<<<(E * EHID + 255) / 256, 256>>>(ea, nn1_w, nn1_b, E);                 // 2
    cudaMemsetAsync(degi, 0, N * sizeof(int));                                              // 3
    cudaMemsetAsync(cnt, 0, NG * sizeof(int));                                              // 4
    count_kernel<<<(E + 255) / 256, 256>>>(ei, batch, E, N);                                // 5
    {
        dim3 g(WE_COLS / 128, (E + 127) / 128);
        we_gemm_kernel<<<g, 256, we_smem>>>(hedge_h, nn2w_h, nn2_b, We_h, E);               // 6 (profiled)
    }
    invdeg_kernel<<<(N + 255) / 256, 256>>>(N);
    scan_kernel<<<1, NG>>>();

    // lin0: h = relu(x @ lin0^T + b); also zeroes agg
    {
        dim3 g(DIMV / BN, (N + BM - 1) / BM);
        gemm_kernel<<<g, 256>>>(x, lin0_w, lin0_b, h, agg, N, DIMV, NFEAT, 1);
    }

    // 3x NNConv + GRU (node_update re-zeroes agg for the next iteration)
    for (int it = 0; it < 3; it++) {
        msg_kernel<<<(E + 7) / 8, 256>>>(ei, E);
        node_update_kernel<<<(N + 127) / 128, 256, nu_smem>>>(conv_b, gru_b_ih, gru_b_hh, N);
    }

    // fused Set2Set + readout
    set2set_kernel<<<NG, 128>>>(lstm_b_ih, lstm_b_hh, lin1_b, lin2_w, lin2_b, y);
}

// round 7
// speedup vs baseline: 1.0334x; 1.0334x over previous
#include <cuda_runtime.h>
#include <cuda_fp16.h>
#include <math.h>
#include <stdint.h>

#define DIMV   64
#define NG     512
#define NNODES 20000
#define NEDGES 60000
#define NFEAT  11
#define EHID   128
#define WE_COLS 4096   // DIM*DIM

// ---------------- scratch ----------------
__device__ __half g_We_h[(size_t)NEDGES * WE_COLS];   // 491 MB
__device__ __half g_hedge_h[NEDGES * EHID];
__device__ __half g_nn2w_h[WE_COLS * EHID];
__device__ __half g_nodew_h[448 * 64];                // [root(64) | Wih(192) | Whh(192)]
__device__ float g_h[NNODES * DIMV];
__device__ float g_agg[NNODES * DIMV];
__device__ float g_invdeg[NNODES];
__device__ int   g_degi[NNODES];
__device__ int   g_cnt[NG];
__device__ int   g_gstart[NG + 1];
__device__ float g_ebuf[NNODES];
__device__ float g_wihT[128 * 256];
__device__ float g_whhT[64 * 256];
__device__ float g_lin1T[128 * 64];

// ---------------- lin0 GEMM (fp32, R4-exact) ----------------
#define BM 64
#define BN 64
#define BKK 16

__global__ void gemm_kernel(const float* __restrict__ A, const float* __restrict__ W,
                            const float* __restrict__ bias,
                            float* __restrict__ C, int M, int Nc, int K, int do_relu)
{
    __shared__ float As[BKK][BM];
    __shared__ float Ws[BKK][BN];

    const int bm = blockIdx.y * BM;
    const int bn = blockIdx.x * BN;
    const int tid = threadIdx.x;
    const int tm = (tid / 16) * 4;
    const int tn = (tid % 16) * 4;

    float acc[4][4];
#pragma unroll
    for (int i = 0; i < 4; i++)
#pragma unroll
        for (int j = 0; j < 4; j++) acc[i][j] = 0.f;

    for (int k0 = 0; k0 < K; k0 += BKK) {
#pragma unroll
        for (int r = 0; r < 4; r++) {
            int idx = tid + r * 256;
            int mm = idx / BKK, kk = idx % BKK;
            int gm = bm + mm, gk = k0 + kk;
            float v = 0.f;
            if (gm < M && gk < K) v = A[(size_t)gm * K + gk];
            As[kk][mm] = v;
        }
#pragma unroll
        for (int r = 0; r < 4; r++) {
            int idx = tid + r * 256;
            int nn = idx / BKK, kk = idx % BKK;
            int gn = bn + nn, gk = k0 + kk;
            float v = 0.f;
            if (gn < Nc && gk < K) v = W[(size_t)gn * K + gk];
            Ws[kk][nn] = v;
        }
        __syncthreads();

#pragma unroll
        for (int kk = 0; kk < BKK; kk++) {
            float a0 = As[kk][tm + 0], a1 = As[kk][tm + 1], a2 = As[kk][tm + 2], a3 = As[kk][tm + 3];
            float b0 = Ws[kk][tn + 0], b1 = Ws[kk][tn + 1], b2 = Ws[kk][tn + 2], b3 = Ws[kk][tn + 3];
            acc[0][0] += a0 * b0; acc[0][1] += a0 * b1; acc[0][2] += a0 * b2; acc[0][3] += a0 * b3;
            acc[1][0] += a1 * b0; acc[1][1] += a1 * b1; acc[1][2] += a1 * b2; acc[1][3] += a1 * b3;
            acc[2][0] += a2 * b0; acc[2][1] += a2 * b1; acc[2][2] += a2 * b2; acc[2][3] += a2 * b3;
            acc[3][0] += a3 * b0; acc[3][1] += a3 * b1; acc[3][2] += a3 * b2; acc[3][3] += a3 * b3;
        }
        __syncthreads();
    }

#pragma unroll
    for (int i = 0; i < 4; i++) {
        int gm = bm + tm + i;
        if (gm >= M) continue;
#pragma unroll
        for (int j = 0; j < 4; j++) {
            int gn = bn + tn + j;
            if (gn >= Nc) continue;
            float v = acc[i][j] + bias[gn];
            if (do_relu) v = fmaxf(v, 0.f);
            C[(size_t)gm * Nc + gn] = v;
        }
    }
}

// ---------------- fused prep ----------------
__global__ void prep_kernel(const float* __restrict__ nn2_w,
                            const float* __restrict__ root_w,
                            const float* __restrict__ wih, const float* __restrict__ whh,
                            const float* __restrict__ lstm_w_ih, const float* __restrict__ lstm_w_hh,
                            const float* __restrict__ lin1_w)
{
    int i = blockIdx.x * blockDim.x + threadIdx.x;
    if (i < WE_COLS * EHID) g_nn2w_h[i] = __float2half(nn2_w[i]);
    if (i < 448 * 64) {
        int row = i >> 6, k = i & 63;
        float v;
        if (row < 64)       v = root_w[row * 64 + k];
        else if (row < 256) v = wih[(row - 64) * 64 + k];
        else                v = whh[(row - 256) * 64 + k];
        g_nodew_h[i] = __float2half(v);
    }
    if (i < 256 * 128) { int r = i / 128, k = i % 128; g_wihT[k * 256 + r] = lstm_w_ih[i]; }
    if (i < 256 * 64)  { int r = i / 64,  k = i % 64;  g_whhT[k * 256 + r] = lstm_w_hh[i]; }
    if (i < 64 * 128)  { int r = i / 128, k = i % 128; g_lin1T[k * 64 + r] = lin1_w[i]; }
}

// ---------------- edge MLP layer 1 ----------------
__global__ void edge_mlp1_kernel(const float* __restrict__ ea,
                                 const float* __restrict__ nn1_w, const float* __restrict__ nn1_b,
                                 int E)
{
    int idx = blockIdx.x * blockDim.x + threadIdx.x;
    if (idx >= E * EHID) return;
    int e = idx / EHID, j = idx % EHID;
    float acc = nn1_b[j];
    const float* w = nn1_w + j * 5;
    const float* a = ea + e * 5;
#pragma unroll
    for (int k = 0; k < 5; k++) acc += a[k] * __ldg(&w[k]);
    g_hedge_h[idx] = __float2half(fmaxf(acc, 0.f));
}

// ---------------- mma helper ----------------
__device__ __forceinline__ void mma16816(float c[4], const uint32_t a[4], uint32_t b0, uint32_t b1)
{
    asm volatile(
        "mma.sync.aligned.m16n8k16.row.col.f32.f16.f16.f32 "
        "{%0,%1,%2,%3}, {%4,%5,%6,%7}, {%8,%9}, {%0,%1,%2,%3};\n"
        : "+f"(c[0]), "+f"(c[1]), "+f"(c[2]), "+f"(c[3])
        : "r"(a[0]), "r"(a[1]), "r"(a[2]), "r"(a[3]), "r"(b0), "r"(b1));
}

// ---------------- big GEMM (R4 version, validated 276us / 2 CTA/SM) ----------------
#define WG_PAD 8
#define WG_LDK (EHID + WG_PAD)

__global__ void __launch_bounds__(256) we_gemm_kernel(
    const __half* __restrict__ A, const __half* __restrict__ B,
    const float* __restrict__ bias, __half* __restrict__ C, int M)
{
    extern __shared__ __half smemh[];
    __half (*As)[WG_LDK] = (__half (*)[WG_LDK])smemh;
    __half (*Bs)[WG_LDK] = (__half (*)[WG_LDK])(smemh + 128 * WG_LDK);

    const int bm = blockIdx.y * 128;
    const int bn = blockIdx.x * 128;
    const int tid = threadIdx.x;
    const int warp = tid >> 5, lane = tid & 31;
    const int wm = (warp & 1) * 64;
    const int wn = (warp >> 1) * 32;

#pragma unroll
    for (int i = 0; i < 8; i++) {
        int idx = tid + i * 256;
        int row = idx >> 4, u = idx & 15;
        int gm = bm + row;
        uint32_t dst = (uint32_t)__cvta_generic_to_shared(&As[row][u * 8]);
        const void* src = A + (size_t)gm * EHID + u * 8;
        int sz = (gm < M) ? 16 : 0;
        asm volatile("cp.async.ca.shared.global [%0], [%1], 16, %2;\n"
                     :: "r"(dst), "l"(src), "r"(sz));
    }
#pragma unroll
    for (int i = 0; i < 8; i++) {
        int idx = tid + i * 256;
        int row = idx >> 4, u = idx & 15;
        uint32_t dst = (uint32_t)__cvta_generic_to_shared(&Bs[row][u * 8]);
        const void* src = B + (size_t)(bn + row) * EHID + u * 8;
        asm volatile("cp.async.ca.shared.global [%0], [%1], 16;\n"
                     :: "r"(dst), "l"(src));
    }
    asm volatile("cp.async.commit_group;\n" ::: "memory");
    asm volatile("cp.async.wait_group 0;\n" ::: "memory");
    __syncthreads();

    float c[4][4][4];
#pragma unroll
    for (int mt = 0; mt < 4; mt++)
#pragma unroll
        for (int nt = 0; nt < 4; nt++)
#pragma unroll
            for (int i = 0; i < 4; i++) c[mt][nt][i] = 0.f;

    const int g = lane >> 3, r = lane & 7;

#pragma unroll
    for (int k0 = 0; k0 < EHID; k0 += 16) {
        uint32_t af[4][4];
#pragma unroll
        for (int mt = 0; mt < 4; mt++) {
            uint32_t addr = (uint32_t)__cvta_generic_to_shared(
                &As[wm + mt * 16 + r + (g & 1) * 8][k0 + (g >> 1) * 8]);
            asm volatile("ldmatrix.sync.aligned.m8n8.x4.shared.b16 {%0,%1,%2,%3}, [%4];"
                         : "=r"(af[mt][0]), "=r"(af[mt][1]), "=r"(af[mt][2]), "=r"(af[mt][3])
                         : "r"(addr));
        }
        uint32_t bf[4][2];
#pragma unroll
        for (int p = 0; p < 2; p++) {
            uint32_t addr = (uint32_t)__cvta_generic_to_shared(
                &Bs[wn + p * 16 + r + (g >> 1) * 8][k0 + (g & 1) * 8]);
            uint32_t b0, b1, b2, b3;
            asm volatile("ldmatrix.sync.aligned.m8n8.x4.shared.b16 {%0,%1,%2,%3}, [%4];"
                         : "=r"(b0), "=r"(b1), "=r"(b2), "=r"(b3) : "r"(addr));
            bf[2 * p][0] = b0; bf[2 * p][1] = b1;
            bf[2 * p + 1][0] = b2; bf[2 * p + 1][1] = b3;
        }
#pragma unroll
        for (int mt = 0; mt < 4; mt++)
#pragma unroll
            for (int nt = 0; nt < 4; nt++)
                mma16816(c[mt][nt], af[mt], bf[nt][0], bf[nt][1]);
    }

#pragma unroll
    for (int mt = 0; mt < 4; mt++) {
        int row0 = bm + wm + mt * 16 + (lane >> 2);
#pragma unroll
        for (int nt = 0; nt < 4; nt++) {
            int gn = bn + wn + nt * 8 + 2 * (lane & 3);
            float b0 = bias[gn], b1 = bias[gn + 1];
            if (row0 < M) {
                __half2 h = __floats2half2_rn(c[mt][nt][0] + b0, c[mt][nt][1] + b1);
                *(__half2*)(C + (size_t)row0 * WE_COLS + gn) = h;
            }
            if (row0 + 8 < M) {
                __half2 h = __floats2half2_rn(c[mt][nt][2] + b0, c[mt][nt][3] + b1);
                *(__half2*)(C + (size_t)(row0 + 8) * WE_COLS + gn) = h;
            }
        }
    }
}

// ---------------- fused node update (R4-exact, no agg rezero) ----------------
#define NU_LD 72

__device__ __forceinline__ void nu_lda(const __half (*sh)[NU_LD], int wm, int k0, int lane, uint32_t af[2][4])
{
    const int g = lane >> 3, r = lane & 7;
#pragma unroll
    for (int mt = 0; mt < 2; mt++) {
        uint32_t addr = (uint32_t)__cvta_generic_to_shared(
            &sh[wm + mt * 16 + r + (g & 1) * 8][k0 + (g >> 1) * 8]);
        asm volatile("ldmatrix.sync.aligned.m8n8.x4.shared.b16 {%0,%1,%2,%3}, [%4];"
                     : "=r"(af[mt][0]), "=r"(af[mt][1]), "=r"(af[mt][2]), "=r"(af[mt][3])
                     : "r"(addr));
    }
}

__device__ __forceinline__ void nu_ldb(const __half (*shW)[NU_LD], int rowbase, int wn, int k0, int lane,
                                       uint32_t bf[4][2])
{
    const int g = lane >> 3, r = lane & 7;
#pragma unroll
    for (int p = 0; p < 2; p++) {
        uint32_t addr = (uint32_t)__cvta_generic_to_shared(
            &shW[rowbase + wn + p * 16 + r + (g >> 1) * 8][k0 + (g & 1) * 8]);
        uint32_t b0, b1, b2, b3;
        asm volatile("ldmatrix.sync.aligned.m8n8.x4.shared.b16 {%0,%1,%2,%3}, [%4];"
                     : "=r"(b0), "=r"(b1), "=r"(b2), "=r"(b3) : "r"(addr));
        bf[2 * p][0] = b0; bf[2 * p][1] = b1;
        bf[2 * p + 1][0] = b2; bf[2 * p + 1][1] = b3;
    }
}

__device__ __forceinline__ void nu_mma(const __half (*shA)[NU_LD], const __half (*shW)[NU_LD],
                                       int rowbase, int wm, int wn, int lane, float c[2][4][4])
{
#pragma unroll
    for (int k0 = 0; k0 < 64; k0 += 16) {
        uint32_t af[2][4];
        nu_lda(shA, wm, k0, lane, af);
        uint32_t bf[4][2];
        nu_ldb(shW, rowbase, wn, k0, lane, bf);
#pragma unroll
        for (int mt = 0; mt < 2; mt++)
#pragma unroll
            for (int nt = 0; nt < 4; nt++)
                mma16816(c[mt][nt], af[mt], bf[nt][0], bf[nt][1]);
    }
}

__device__ __forceinline__ float sigmoidf_(float x) { return 1.f / (1.f + expf(-x)); }

__global__ void __launch_bounds__(256) node_update_kernel(
    const float* __restrict__ conv_b, const float* __restrict__ b_ih, const float* __restrict__ b_hh,
    int N)
{
    extern __shared__ __half sm_[];
    __half (*shW)[NU_LD] = (__half (*)[NU_LD])sm_;
    __half (*shH)[NU_LD] = (__half (*)[NU_LD])(sm_ + 448 * NU_LD);
    __half (*shM)[NU_LD] = (__half (*)[NU_LD])(sm_ + (448 + 128) * NU_LD);

    const int bm = blockIdx.x * 128;
    const int tid = threadIdx.x;
    const int warp = tid >> 5, lane = tid & 31;
    const int wm = (warp & 3) * 32;
    const int wn = (warp >> 2) * 32;

#pragma unroll
    for (int i = 0; i < 14; i++) {
        int idx = tid + i * 256;
        int row = idx >> 3, u = idx & 7;
        uint32_t dst = (uint32_t)__cvta_generic_to_shared(&shW[row][u * 8]);
        const void* src = g_nodew_h + (size_t)row * 64 + u * 8;
        asm volatile("cp.async.ca.shared.global [%0], [%1], 16;\n" :: "r"(dst), "l"(src));
    }
    asm volatile("cp.async.commit_group;\n" ::: "memory");

#pragma unroll
    for (int i = 0; i < 8; i++) {
        int idx = tid + i * 256;
        int row = idx >> 4, u = idx & 15;
        int grow = bm + row;
        float4 v = make_float4(0.f, 0.f, 0.f, 0.f);
        if (grow < N) v = *(const float4*)(g_h + (size_t)grow * DIMV + u * 4);
        *(__half2*)(&shH[row][u * 4])     = __floats2half2_rn(v.x, v.y);
        *(__half2*)(&shH[row][u * 4 + 2]) = __floats2half2_rn(v.z, v.w);
    }
    asm volatile("cp.async.wait_group 0;\n" ::: "memory");
    __syncthreads();

    // stage1: m = relu(agg*invdeg + h@root^T + conv_b)
    {
        float c[2][4][4];
#pragma unroll
        for (int mt = 0; mt < 2; mt++)
#pragma unroll
            for (int nt = 0; nt < 4; nt++)
#pragma unroll
                for (int i = 0; i < 4; i++) c[mt][nt][i] = 0.f;
        nu_mma(shH, shW, 0, wm, wn, lane, c);

#pragma unroll
        for (int mt = 0; mt < 2; mt++) {
            int lrow0 = wm + mt * 16 + (lane >> 2);
#pragma unroll
            for (int nt = 0; nt < 4; nt++) {
                int col = wn + nt * 8 + 2 * (lane & 3);
                float cb0 = conv_b[col], cb1 = conv_b[col + 1];
#pragma unroll
                for (int hrow = 0; hrow < 2; hrow++) {
                    int lrow = lrow0 + hrow * 8;
                    int grow = bm + lrow;
                    float a0 = 0.f, a1 = 0.f;
                    if (grow < N) {
                        float id = g_invdeg[grow];
                        float2 ag = *(const float2*)(g_agg + (size_t)grow * DIMV + col);
                        a0 = ag.x * id; a1 = ag.y * id;
                    }
                    float m0 = fmaxf(c[mt][nt][2 * hrow]     + a0 + cb0, 0.f);
                    float m1 = fmaxf(c[mt][nt][2 * hrow + 1] + a1 + cb1, 0.f);
                    *(__half2*)(&shM[lrow][col]) = __floats2half2_rn(m0, m1);
                }
            }
        }
    }
    __syncthreads();

    // gate r
    float rfr[2][4][4];
#pragma unroll
    for (int mt = 0; mt < 2; mt++)
#pragma unroll
        for (int nt = 0; nt < 4; nt++)
#pragma unroll
            for (int i = 0; i < 4; i++) rfr[mt][nt][i] = 0.f;
    nu_mma(shM, shW, 64, wm, wn, lane, rfr);
    nu_mma(shH, shW, 256, wm, wn, lane, rfr);
#pragma unroll
    for (int mt = 0; mt < 2; mt++)
#pragma unroll
        for (int nt = 0; nt < 4; nt++) {
            int col = wn + nt * 8 + 2 * (lane & 3);
            float bb0 = b_ih[col] + b_hh[col];
            float bb1 = b_ih[col + 1] + b_hh[col + 1];
            rfr[mt][nt][0] = sigmoidf_(rfr[mt][nt][0] + bb0);
            rfr[mt][nt][1] = sigmoidf_(rfr[mt][nt][1] + bb1);
            rfr[mt][nt][2] = sigmoidf_(rfr[mt][nt][2] + bb0);
            rfr[mt][nt][3] = sigmoidf_(rfr[mt][nt][3] + bb1);
        }

    // gate n
    float nfr[2][4][4];
    {
        float cin[2][4][4], chn[2][4][4];
#pragma unroll
        for (int mt = 0; mt < 2; mt++)
#pragma unroll
            for (int nt = 0; nt < 4; nt++)
#pragma unroll
                for (int i = 0; i < 4; i++) { cin[mt][nt][i] = 0.f; chn[mt][nt][i] = 0.f; }
        nu_mma(shM, shW, 64 + 128, wm, wn, lane, cin);
        nu_mma(shH, shW, 256 + 128, wm, wn, lane, chn);
#pragma unroll
        for (int mt = 0; mt < 2; mt++)
#pragma unroll
            for (int nt = 0; nt < 4; nt++) {
                int col = wn + nt * 8 + 2 * (lane & 3);
                float bi0 = b_ih[128 + col], bi1 = b_ih[128 + col + 1];
                float bh0 = b_hh[128 + col], bh1 = b_hh[128 + col + 1];
                nfr[mt][nt][0] = tanhf(cin[mt][nt][0] + bi0 + rfr[mt][nt][0] * (chn[mt][nt][0] + bh0));
                nfr[mt][nt][1] = tanhf(cin[mt][nt][1] + bi1 + rfr[mt][nt][1] * (chn[mt][nt][1] + bh1));
                nfr[mt][nt][2] = tanhf(cin[mt][nt][2] + bi0 + rfr[mt][nt][2] * (chn[mt][nt][2] + bh0));
                nfr[mt][nt][3] = tanhf(cin[mt][nt][3] + bi1 + rfr[mt][nt][3] * (chn[mt][nt][3] + bh1));
            }
    }

    // gate z + h' = (1-z)*n + z*h_old
    {
        float cz[2][4][4];
#pragma unroll
        for (int mt = 0; mt < 2; mt++)
#pragma unroll
            for (int nt = 0; nt < 4; nt++)
#pragma unroll
                for (int i = 0; i < 4; i++) cz[mt][nt][i] = 0.f;
        nu_mma(shM, shW, 64 + 64, wm, wn, lane, cz);
        nu_mma(shH, shW, 256 + 64, wm, wn, lane, cz);
#pragma unroll
        for (int mt = 0; mt < 2; mt++) {
            int lrow0 = wm + mt * 16 + (lane >> 2);
#pragma unroll
            for (int nt = 0; nt < 4; nt++) {
                int col = wn + nt * 8 + 2 * (lane & 3);
                float bb0 = b_ih[64 + col] + b_hh[64 + col];
                float bb1 = b_ih[64 + col + 1] + b_hh[64 + col + 1];
#pragma unroll
                for (int hrow = 0; hrow < 2; hrow++) {
                    int grow = bm + lrow0 + hrow * 8;
                    if (grow >= N) continue;
                    float z0 = sigmoidf_(cz[mt][nt][2 * hrow]     + bb0);
                    float z1 = sigmoidf_(cz[mt][nt][2 * hrow + 1] + bb1);
                    float2 ho = *(const float2*)(g_h + (size_t)grow * DIMV + col);
                    float2 hn_;
                    hn_.x = (1.f - z0) * nfr[mt][nt][2 * hrow]     + z0 * ho.x;
                    hn_.y = (1.f - z1) * nfr[mt][nt][2 * hrow + 1] + z1 * ho.y;
                    *(float2*)(g_h + (size_t)grow * DIMV + col) = hn_;
                }
            }
        }
    }
}

// ---------------- bookkeeping ----------------
__global__ void count_kernel(const int* __restrict__ ei, const int* __restrict__ batch, int E, int N)
{
    int i = blockIdx.x * blockDim.x + threadIdx.x;
    if (i < E) atomicAdd(&g_degi[ei[E + i]], 1);
    if (i < N) atomicAdd(&g_cnt[batch[i]], 1);
}

__global__ void invdeg_kernel(int N)
{
    int i = blockIdx.x * blockDim.x + threadIdx.x;
    if (i < N) g_invdeg[i] = 1.f / fmaxf((float)g_degi[i], 1.f);
}

__global__ void scan_kernel()
{
    __shared__ int s[NG];
    int t = threadIdx.x;
    s[t] = g_cnt[t];
    __syncthreads();
    for (int off = 1; off < NG; off <<= 1) {
        int v = (t >= off) ? s[t - off] : 0;
        __syncthreads();
        s[t] += v;
        __syncthreads();
    }
    if (t == 0) g_gstart[0] = 0;
    g_gstart[t + 1] = s[t];
}

// ---------------- msg v2: uint4 loads (16 LDG.128/step-loop), shfl reduce, 8 atomics/lane ----
__global__ void msg_kernel(const int* __restrict__ ei, int E)
{
    const int w    = threadIdx.x >> 5;     // 8 edges per block
    const int lane = threadIdx.x & 31;
    const int e    = blockIdx.x * 8 + w;
    __shared__ float s_a[8][DIMV];

    if (e >= E) return;
    int src = ei[e];
    int dst = ei[E + e];
    s_a[w][lane]      = g_h[src * DIMV + lane];
    s_a[w][lane + 32] = g_h[src * DIMV + lane + 32];
    __syncwarp();

    const int o8 = lane & 7;     // this lane's uint4 slot within a row (8 output cols)
    const int ig = lane >> 3;    // row offset within group of 4

    float acc[8];
#pragma unroll
    for (int j = 0; j < 8; j++) acc[j] = 0.f;

    const uint4* __restrict__ wp = (const uint4*)(g_We_h + (size_t)e * WE_COLS);
#pragma unroll
    for (int step = 0; step < 16; step++) {
        int i = step * 4 + ig;
        uint4 v = wp[i * 8 + o8];           // warp reads 512 contiguous bytes per step
        float a = s_a[w][i];
        float2 f0 = __half22float2(*(__half2*)&v.x);
        float2 f1 = __half22float2(*(__half2*)&v.y);
        float2 f2 = __half22float2(*(__half2*)&v.z);
        float2 f3 = __half22float2(*(__half2*)&v.w);
        acc[0] = fmaf(a, f0.x, acc[0]); acc[1] = fmaf(a, f0.y, acc[1]);
        acc[2] = fmaf(a, f1.x, acc[2]); acc[3] = fmaf(a, f1.y, acc[3]);
        acc[4] = fmaf(a, f2.x, acc[4]); acc[5] = fmaf(a, f2.y, acc[5]);
        acc[6] = fmaf(a, f3.x, acc[6]); acc[7] = fmaf(a, f3.y, acc[7]);
    }

    // combine the 4 i-groups: lanes l, l^8, l^16(, ^24) share the same o-range
#pragma unroll
    for (int j = 0; j < 8; j++) {
        acc[j] += __shfl_xor_sync(0xffffffff, acc[j], 8);
        acc[j] += __shfl_xor_sync(0xffffffff, acc[j], 16);
    }

    if (lane < 8) {
        float* dp = g_agg + (size_t)dst * DIMV + lane * 8;
#pragma unroll
        for (int j = 0; j < 8; j++) atomicAdd(&dp[j], acc[j]);
    }
}

// ---------------- fused Set2Set (3 steps) + readout ----------------
__global__ void __launch_bounds__(128) set2set_kernel(
    const float* __restrict__ b_ih, const float* __restrict__ b_hh,
    const float* __restrict__ lin1_b, const float* __restrict__ lin2_w,
    const float* __restrict__ lin2_b, float* __restrict__ y)
{
    const int b = blockIdx.x, t = threadIdx.x;
    const int s = g_gstart[b], e_end = g_gstart[b + 1];

    __shared__ float qs[2 * DIMV];
    __shared__ float hsv[DIMV];
    __shared__ float csv[DIMV];
    __shared__ float gates[4 * DIMV];
    __shared__ float red[128];

    qs[t] = 0.f;
    if (t < 64) { hsv[t] = 0.f; csv[t] = 0.f; }
    __syncthreads();

    for (int step = 0; step < 3; step++) {
#pragma unroll
        for (int gsel = 0; gsel < 2; gsel++) {
            int gidx = t + gsel * 128;
            float acc = b_ih[gidx] + b_hh[gidx];
#pragma unroll 8
            for (int k = 0; k < 128; k++) acc += qs[k] * g_wihT[k * 256 + gidx];
#pragma unroll 8
            for (int k = 0; k < 64; k++)  acc += hsv[k] * g_whhT[k * 256 + gidx];
            gates[gidx] = acc;
        }
        __syncthreads();
        if (t < 64) {
            float i = sigmoidf_(gates[t]);
            float f = sigmoidf_(gates[64 + t]);
            float g = tanhf(gates[128 + t]);
            float o = sigmoidf_(gates[192 + t]);
            float c = f * csv[t] + i * g;
            csv[t] = c;
            hsv[t] = o * tanhf(c);
        }
        __syncthreads();

        float lmax = -1e30f;
        for (int n = s + t; n < e_end; n += 128) {
            const float* row = g_h + (size_t)n * DIMV;
            float acc = 0.f;
#pragma unroll 8
            for (int i = 0; i < DIMV; i++) acc += row[i] * hsv[i];
            g_ebuf[n] = acc;
            lmax = fmaxf(lmax, acc);
        }
        red[t] = lmax; __syncthreads();
        for (int st = 64; st > 0; st >>= 1) { if (t < st) red[t] = fmaxf(red[t], red[t + st]); __syncthreads(); }
        float gmax = red[0];
        __syncthreads();

        float lsum = 0.f;
        for (int n = s + t; n < e_end; n += 128) {
            float a = expf(g_ebuf[n] - gmax);
            g_ebuf[n] = a;
            lsum += a;
        }
        red[t] = lsum; __syncthreads();
        for (int st = 64; st > 0; st >>= 1) { if (t < st) red[t] += red[t + st]; __syncthreads(); }
        float S = red[0];
        __syncthreads();

        {
            int d = t & 63, half = t >> 6;
            float r = 0.f;
            for (int n = s + half; n < e_end; n += 2)
                r += g_ebuf[n] * g_h[(size_t)n * DIMV + d];
            red[t] = r;
        }
        __syncthreads();
        if (t < 64) {
            float rr = red[t] + red[t + 64];
            qs[t] = hsv[t];
            qs[64 + t] = (e_end > s) ? (rr / S) : 0.f;
        }
        __syncthreads();
    }

    if (t < 64) {
        float acc = lin1_b[t];
#pragma unroll 8
        for (int k = 0; k < 128; k++) acc += qs[k] * g_lin1T[k * 64 + t];
        float z = fmaxf(acc, 0.f);
        red[t] = z * lin2_w[t];
    }
    __syncthreads();
    for (int st = 32; st > 0; st >>= 1) { if (t < st) red[t] += red[t + st]; __syncthreads(); }
    if (t == 0) y[b] = red[0] + lin2_b[0];
}

// ======================================================================================
extern "C" void kernel_launch(void* const* d_in, const int* in_sizes, int n_in,
                              void* d_out, int out_size)
{
    const float* x        = (const float*)d_in[0];
    const int*   ei       = (const int*)  d_in[1];
    const float* ea       = (const float*)d_in[2];
    const int*   batch    = (const int*)  d_in[3];
    const float* lin0_w   = (const float*)d_in[4];
    const float* lin0_b   = (const float*)d_in[5];
    const float* nn1_w    = (const float*)d_in[6];
    const float* nn1_b    = (const float*)d_in[7];
    const float* nn2_w    = (const float*)d_in[8];
    const float* nn2_b    = (const float*)d_in[9];
    const float* root_w   = (const float*)d_in[10];
    const float* conv_b   = (const float*)d_in[11];
    const float* gru_w_ih = (const float*)d_in[12];
    const float* gru_w_hh = (const float*)d_in[13];
    const float* gru_b_ih = (const float*)d_in[14];
    const float* gru_b_hh = (const float*)d_in[15];
    const float* lstm_w_ih= (const float*)d_in[16];
    const float* lstm_w_hh= (const float*)d_in[17];
    const float* lstm_b_ih= (const float*)d_in[18];
    const float* lstm_b_hh= (const float*)d_in[19];
    const float* lin1_w   = (const float*)d_in[20];
    const float* lin1_b   = (const float*)d_in[21];
    const float* lin2_w   = (const float*)d_in[22];
    const float* lin2_b   = (const float*)d_in[23];
    float* y = (float*)d_out;

    const int N = NNODES, E = NEDGES;

    __half *We_h, *hedge_h, *nn2w_h;
    float *h, *agg;
    int *degi, *cnt;
    cudaGetSymbolAddress((void**)&We_h, g_We_h);
    cudaGetSymbolAddress((void**)&hedge_h, g_hedge_h);
    cudaGetSymbolAddress((void**)&nn2w_h, g_nn2w_h);
    cudaGetSymbolAddress((void**)&h, g_h);
    cudaGetSymbolAddress((void**)&agg, g_agg);
    cudaGetSymbolAddress((void**)&degi, g_degi);
    cudaGetSymbolAddress((void**)&cnt, g_cnt);

    const int we_smem = 2 * 128 * WG_LDK * (int)sizeof(__half);  // ~68 KB (2 CTA/SM)
    cudaFuncSetAttribute(we_gemm_kernel, cudaFuncAttributeMaxDynamicSharedMemorySize, we_smem);
    const int nu_smem = (448 + 128 + 128) * NU_LD * (int)sizeof(__half);
    cudaFuncSetAttribute(node_update_kernel, cudaFuncAttributeMaxDynamicSharedMemorySize, nu_smem);

    // launches arranged so msg_kernel (iter 1) is #6 for ncu -s 5 -c 1
    prep_kernel<<<(WE_COLS * EHID + 255) / 256, 256>>>(nn2_w, root_w, gru_w_ih, gru_w_hh,
                                                       lstm_w_ih, lstm_w_hh, lin1_w);        // 1
    edge_mlp1_kernel<<<(E * EHID + 255) / 256, 256>>>(ea, nn1_w, nn1_b, E);                  // 2
    {
        dim3 g(WE_COLS / 128, (E + 127) / 128);
        we_gemm_kernel<<<g, 256, we_smem>>>(hedge_h, nn2w_h, nn2_b, We_h, E);                // 3
    }
    {
        dim3 g(DIMV / BN, (N + BM - 1) / BM);
        gemm_kernel<<<g, 256>>>(x, lin0_w, lin0_b, h, N, DIMV, NFEAT, 1);                    // 4
    }
    cudaMemsetAsync(agg, 0, (size_t)N * DIMV * sizeof(float));                               // 5
    msg_kernel<<<(E + 7) / 8, 256>>>(ei, E);                                                 // 6 (profiled)

    cudaMemsetAsync(degi, 0, N * sizeof(int));
    cudaMemsetAsync(cnt, 0, NG * sizeof(int));
    count_kernel<<<(E + 255) / 256, 256>>>(ei, batch, E, N);
    invdeg_kernel<<<(N + 255) / 256, 256>>>(N);
    scan_kernel<<<1, NG>>>();

    node_update_kernel<<<(N + 127) / 128, 256, nu_smem>>>(conv_b, gru_b_ih, gru_b_hh, N);    // iter 1

    for (int it = 1; it < 3; it++) {
        cudaMemsetAsync(agg, 0, (size_t)N * DIMV * sizeof(float));
        msg_kernel<<<(E + 7) / 8, 256>>>(ei, E);
        node_update_kernel<<<(N + 127) / 128, 256, nu_smem>>>(conv_b, gru_b_ih, gru_b_hh, N);
    }

    set2set_kernel<<<NG, 128>>>(lstm_b_ih, lstm_b_hh, lin1_b, lin2_w, lin2_b, y);
}

// round 8
// speedup vs baseline: 1.0442x; 1.0104x over previous
#include <cuda_runtime.h>
#include <cuda_fp16.h>
#include <math.h>
#include <stdint.h>

#define DIMV   64
#define NG     512
#define NNODES 20000
#define NEDGES 60000
#define NFEAT  11
#define EHID   128
#define WE_COLS 4096   // DIM*DIM

// ---------------- scratch ----------------
__device__ __half g_We_h[(size_t)NEDGES * WE_COLS];   // 491 MB
__device__ __half g_hedge_h[NEDGES * EHID];
__device__ __half g_nn2w_h[WE_COLS * EHID];
__device__ __half g_nodew_h[448 * 64];                // [root(64) | Wih(192) | Whh(192)]
__device__ float g_h[NNODES * DIMV];
__device__ float g_agg[NNODES * DIMV];
__device__ float g_invdeg[NNODES];
__device__ int   g_degi[NNODES];
__device__ int   g_cnt[NG];
__device__ int   g_gstart[NG + 1];
__device__ float g_ebuf[NNODES];
__device__ float g_wihT[128 * 256];
__device__ float g_whhT[64 * 256];
__device__ float g_lin1T[128 * 64];

// ---------------- lin0 GEMM (fp32) ----------------
#define BM 64
#define BN 64
#define BKK 16

__global__ void gemm_kernel(const float* __restrict__ A, const float* __restrict__ W,
                            const float* __restrict__ bias,
                            float* __restrict__ C, int M, int Nc, int K, int do_relu)
{
    __shared__ float As[BKK][BM];
    __shared__ float Ws[BKK][BN];

    const int bm = blockIdx.y * BM;
    const int bn = blockIdx.x * BN;
    const int tid = threadIdx.x;
    const int tm = (tid / 16) * 4;
    const int tn = (tid % 16) * 4;

    float acc[4][4];
#pragma unroll
    for (int i = 0; i < 4; i++)
#pragma unroll
        for (int j = 0; j < 4; j++) acc[i][j] = 0.f;

    for (int k0 = 0; k0 < K; k0 += BKK) {
#pragma unroll
        for (int r = 0; r < 4; r++) {
            int idx = tid + r * 256;
            int mm = idx / BKK, kk = idx % BKK;
            int gm = bm + mm, gk = k0 + kk;
            float v = 0.f;
            if (gm < M && gk < K) v = A[(size_t)gm * K + gk];
            As[kk][mm] = v;
        }
#pragma unroll
        for (int r = 0; r < 4; r++) {
            int idx = tid + r * 256;
            int nn = idx / BKK, kk = idx % BKK;
            int gn = bn + nn, gk = k0 + kk;
            float v = 0.f;
            if (gn < Nc && gk < K) v = W[(size_t)gn * K + gk];
            Ws[kk][nn] = v;
        }
        __syncthreads();

#pragma unroll
        for (int kk = 0; kk < BKK; kk++) {
            float a0 = As[kk][tm + 0], a1 = As[kk][tm + 1], a2 = As[kk][tm + 2], a3 = As[kk][tm + 3];
            float b0 = Ws[kk][tn + 0], b1 = Ws[kk][tn + 1], b2 = Ws[kk][tn + 2], b3 = Ws[kk][tn + 3];
            acc[0][0] += a0 * b0; acc[0][1] += a0 * b1; acc[0][2] += a0 * b2; acc[0][3] += a0 * b3;
            acc[1][0] += a1 * b0; acc[1][1] += a1 * b1; acc[1][2] += a1 * b2; acc[1][3] += a1 * b3;
            acc[2][0] += a2 * b0; acc[2][1] += a2 * b1; acc[2][2] += a2 * b2; acc[2][3] += a2 * b3;
            acc[3][0] += a3 * b0; acc[3][1] += a3 * b1; acc[3][2] += a3 * b2; acc[3][3] += a3 * b3;
        }
        __syncthreads();
    }

#pragma unroll
    for (int i = 0; i < 4; i++) {
        int gm = bm + tm + i;
        if (gm >= M) continue;
#pragma unroll
        for (int j = 0; j < 4; j++) {
            int gn = bn + tn + j;
            if (gn >= Nc) continue;
            float v = acc[i][j] + bias[gn];
            if (do_relu) v = fmaxf(v, 0.f);
            C[(size_t)gm * Nc + gn] = v;
        }
    }
}

// ---------------- fused prep ----------------
__global__ void prep_kernel(const float* __restrict__ nn2_w,
                            const float* __restrict__ root_w,
                            const float* __restrict__ wih, const float* __restrict__ whh,
                            const float* __restrict__ lstm_w_ih, const float* __restrict__ lstm_w_hh,
                            const float* __restrict__ lin1_w)
{
    int i = blockIdx.x * blockDim.x + threadIdx.x;
    if (i < WE_COLS * EHID) g_nn2w_h[i] = __float2half(nn2_w[i]);
    if (i < 448 * 64) {
        int row = i >> 6, k = i & 63;
        float v;
        if (row < 64)       v = root_w[row * 64 + k];
        else if (row < 256) v = wih[(row - 64) * 64 + k];
        else                v = whh[(row - 256) * 64 + k];
        g_nodew_h[i] = __float2half(v);
    }
    if (i < 256 * 128) { int r = i / 128, k = i % 128; g_wihT[k * 256 + r] = lstm_w_ih[i]; }
    if (i < 256 * 64)  { int r = i / 64,  k = i % 64;  g_whhT[k * 256 + r] = lstm_w_hh[i]; }
    if (i < 64 * 128)  { int r = i / 128, k = i % 128; g_lin1T[k * 64 + r] = lin1_w[i]; }
}

// ---------------- edge MLP layer 1 ----------------
__global__ void edge_mlp1_kernel(const float* __restrict__ ea,
                                 const float* __restrict__ nn1_w, const float* __restrict__ nn1_b,
                                 int E)
{
    int idx = blockIdx.x * blockDim.x + threadIdx.x;
    if (idx >= E * EHID) return;
    int e = idx / EHID, j = idx % EHID;
    float acc = nn1_b[j];
    const float* w = nn1_w + j * 5;
    const float* a = ea + e * 5;
#pragma unroll
    for (int k = 0; k < 5; k++) acc += a[k] * __ldg(&w[k]);
    g_hedge_h[idx] = __float2half(fmaxf(acc, 0.f));
}

// ---------------- mma helper ----------------
__device__ __forceinline__ void mma16816(float c[4], const uint32_t a[4], uint32_t b0, uint32_t b1)
{
    asm volatile(
        "mma.sync.aligned.m16n8k16.row.col.f32.f16.f16.f32 "
        "{%0,%1,%2,%3}, {%4,%5,%6,%7}, {%8,%9}, {%0,%1,%2,%3};\n"
        : "+f"(c[0]), "+f"(c[1]), "+f"(c[2]), "+f"(c[3])
        : "r"(a[0]), "r"(a[1]), "r"(a[2]), "r"(a[3]), "r"(b0), "r"(b1));
}

// ---------------- big GEMM v4: 128x128 block, 128 threads (4 warps), warp tile 64x64 ----------
// Same 68 KB smem as R4 (>=2, likely 3 CTAs/SM) but 0.25 LDSM/MMA instead of 0.375.
#define WG_PAD 8
#define WG_LDK (EHID + WG_PAD)

__global__ void __launch_bounds__(128) we_gemm_kernel(
    const __half* __restrict__ A, const __half* __restrict__ B,
    const float* __restrict__ bias, __half* __restrict__ C, int M)
{
    extern __shared__ __half smemh[];
    __half (*As)[WG_LDK] = (__half (*)[WG_LDK])smemh;
    __half (*Bs)[WG_LDK] = (__half (*)[WG_LDK])(smemh + 128 * WG_LDK);

    const int bm = blockIdx.y * 128;
    const int bn = blockIdx.x * 128;
    const int tid = threadIdx.x;               // 128 threads
    const int warp = tid >> 5, lane = tid & 31;
    const int wm = (warp & 1) * 64;            // 2 warps along M
    const int wn = (warp >> 1) * 64;           // 2 warps along N

    // A tile: 128 rows x 16 chunks(16B) = 2048 chunks, 16 per thread
#pragma unroll
    for (int i = 0; i < 16; i++) {
        int idx = tid + i * 128;
        int row = idx >> 4, u = idx & 15;
        int gm = bm + row;
        uint32_t dst = (uint32_t)__cvta_generic_to_shared(&As[row][u * 8]);
        const void* src = A + (size_t)gm * EHID + u * 8;
        int sz = (gm < M) ? 16 : 0;
        asm volatile("cp.async.ca.shared.global [%0], [%1], 16, %2;\n"
                     :: "r"(dst), "l"(src), "r"(sz));
    }
    // B tile: 128 rows x 16 chunks = 2048 chunks, 16 per thread
#pragma unroll
    for (int i = 0; i < 16; i++) {
        int idx = tid + i * 128;
        int row = idx >> 4, u = idx & 15;
        uint32_t dst = (uint32_t)__cvta_generic_to_shared(&Bs[row][u * 8]);
        const void* src = B + (size_t)(bn + row) * EHID + u * 8;
        asm volatile("cp.async.ca.shared.global [%0], [%1], 16;\n"
                     :: "r"(dst), "l"(src));
    }
    asm volatile("cp.async.commit_group;\n" ::: "memory");
    asm volatile("cp.async.wait_group 0;\n" ::: "memory");
    __syncthreads();

    float c[4][8][4];
#pragma unroll
    for (int mt = 0; mt < 4; mt++)
#pragma unroll
        for (int nt = 0; nt < 8; nt++)
#pragma unroll
            for (int i = 0; i < 4; i++) c[mt][nt][i] = 0.f;

    const int g = lane >> 3, r = lane & 7;

#pragma unroll
    for (int k0 = 0; k0 < EHID; k0 += 16) {
        uint32_t af[4][4];
#pragma unroll
        for (int mt = 0; mt < 4; mt++) {
            uint32_t addr = (uint32_t)__cvta_generic_to_shared(
                &As[wm + mt * 16 + r + (g & 1) * 8][k0 + (g >> 1) * 8]);
            asm volatile("ldmatrix.sync.aligned.m8n8.x4.shared.b16 {%0,%1,%2,%3}, [%4];"
                         : "=r"(af[mt][0]), "=r"(af[mt][1]), "=r"(af[mt][2]), "=r"(af[mt][3])
                         : "r"(addr));
        }
        uint32_t bf[8][2];
#pragma unroll
        for (int p = 0; p < 4; p++) {
            uint32_t addr = (uint32_t)__cvta_generic_to_shared(
                &Bs[wn + p * 16 + r + (g >> 1) * 8][k0 + (g & 1) * 8]);
            uint32_t b0, b1, b2, b3;
            asm volatile("ldmatrix.sync.aligned.m8n8.x4.shared.b16 {%0,%1,%2,%3}, [%4];"
                         : "=r"(b0), "=r"(b1), "=r"(b2), "=r"(b3) : "r"(addr));
            bf[2 * p][0] = b0; bf[2 * p][1] = b1;
            bf[2 * p + 1][0] = b2; bf[2 * p + 1][1] = b3;
        }
#pragma unroll
        for (int mt = 0; mt < 4; mt++)
#pragma unroll
            for (int nt = 0; nt < 8; nt++)
                mma16816(c[mt][nt], af[mt], bf[nt][0], bf[nt][1]);
    }

    // epilogue: + bias, convert to fp16
#pragma unroll
    for (int mt = 0; mt < 4; mt++) {
        int row0 = bm + wm + mt * 16 + (lane >> 2);
#pragma unroll
        for (int nt = 0; nt < 8; nt++) {
            int gn = bn + wn + nt * 8 + 2 * (lane & 3);
            float b0 = bias[gn], b1 = bias[gn + 1];
            if (row0 < M) {
                __half2 h = __floats2half2_rn(c[mt][nt][0] + b0, c[mt][nt][1] + b1);
                *(__half2*)(C + (size_t)row0 * WE_COLS + gn) = h;
            }
            if (row0 + 8 < M) {
                __half2 h = __floats2half2_rn(c[mt][nt][2] + b0, c[mt][nt][3] + b1);
                *(__half2*)(C + (size_t)(row0 + 8) * WE_COLS + gn) = h;
            }
        }
    }
}

// ---------------- fused node update (R4-exact) ----------------
#define NU_LD 72

__device__ __forceinline__ void nu_lda(const __half (*sh)[NU_LD], int wm, int k0, int lane, uint32_t af[2][4])
{
    const int g = lane >> 3, r = lane & 7;
#pragma unroll
    for (int mt = 0; mt < 2; mt++) {
        uint32_t addr = (uint32_t)__cvta_generic_to_shared(
            &sh[wm + mt * 16 + r + (g & 1) * 8][k0 + (g >> 1) * 8]);
        asm volatile("ldmatrix.sync.aligned.m8n8.x4.shared.b16 {%0,%1,%2,%3}, [%4];"
                     : "=r"(af[mt][0]), "=r"(af[mt][1]), "=r"(af[mt][2]), "=r"(af[mt][3])
                     : "r"(addr));
    }
}

__device__ __forceinline__ void nu_ldb(const __half (*shW)[NU_LD], int rowbase, int wn, int k0, int lane,
                                       uint32_t bf[4][2])
{
    const int g = lane >> 3, r = lane & 7;
#pragma unroll
    for (int p = 0; p < 2; p++) {
        uint32_t addr = (uint32_t)__cvta_generic_to_shared(
            &shW[rowbase + wn + p * 16 + r + (g >> 1) * 8][k0 + (g & 1) * 8]);
        uint32_t b0, b1, b2, b3;
        asm volatile("ldmatrix.sync.aligned.m8n8.x4.shared.b16 {%0,%1,%2,%3}, [%4];"
                     : "=r"(b0), "=r"(b1), "=r"(b2), "=r"(b3) : "r"(addr));
        bf[2 * p][0] = b0; bf[2 * p][1] = b1;
        bf[2 * p + 1][0] = b2; bf[2 * p + 1][1] = b3;
    }
}

__device__ __forceinline__ void nu_mma(const __half (*shA)[NU_LD], const __half (*shW)[NU_LD],
                                       int rowbase, int wm, int wn, int lane, float c[2][4][4])
{
#pragma unroll
    for (int k0 = 0; k0 < 64; k0 += 16) {
        uint32_t af[2][4];
        nu_lda(shA, wm, k0, lane, af);
        uint32_t bf[4][2];
        nu_ldb(shW, rowbase, wn, k0, lane, bf);
#pragma unroll
        for (int mt = 0; mt < 2; mt++)
#pragma unroll
            for (int nt = 0; nt < 4; nt++)
                mma16816(c[mt][nt], af[mt], bf[nt][0], bf[nt][1]);
    }
}

__device__ __forceinline__ float sigmoidf_(float x) { return 1.f / (1.f + expf(-x)); }

__global__ void __launch_bounds__(256) node_update_kernel(
    const float* __restrict__ conv_b, const float* __restrict__ b_ih, const float* __restrict__ b_hh,
    int N)
{
    extern __shared__ __half sm_[];
    __half (*shW)[NU_LD] = (__half (*)[NU_LD])sm_;
    __half (*shH)[NU_LD] = (__half (*)[NU_LD])(sm_ + 448 * NU_LD);
    __half (*shM)[NU_LD] = (__half (*)[NU_LD])(sm_ + (448 + 128) * NU_LD);

    const int bm = blockIdx.x * 128;
    const int tid = threadIdx.x;
    const int warp = tid >> 5, lane = tid & 31;
    const int wm = (warp & 3) * 32;
    const int wn = (warp >> 2) * 32;

#pragma unroll
    for (int i = 0; i < 14; i++) {
        int idx = tid + i * 256;
        int row = idx >> 3, u = idx & 7;
        uint32_t dst = (uint32_t)__cvta_generic_to_shared(&shW[row][u * 8]);
        const void* src = g_nodew_h + (size_t)row * 64 + u * 8;
        asm volatile("cp.async.ca.shared.global [%0], [%1], 16;\n" :: "r"(dst), "l"(src));
    }
    asm volatile("cp.async.commit_group;\n" ::: "memory");

#pragma unroll
    for (int i = 0; i < 8; i++) {
        int idx = tid + i * 256;
        int row = idx >> 4, u = idx & 15;
        int grow = bm + row;
        float4 v = make_float4(0.f, 0.f, 0.f, 0.f);
        if (grow < N) v = *(const float4*)(g_h + (size_t)grow * DIMV + u * 4);
        *(__half2*)(&shH[row][u * 4])     = __floats2half2_rn(v.x, v.y);
        *(__half2*)(&shH[row][u * 4 + 2]) = __floats2half2_rn(v.z, v.w);
    }
    asm volatile("cp.async.wait_group 0;\n" ::: "memory");
    __syncthreads();

    // stage1: m = relu(agg*invdeg + h@root^T + conv_b)
    {
        float c[2][4][4];
#pragma unroll
        for (int mt = 0; mt < 2; mt++)
#pragma unroll
            for (int nt = 0; nt < 4; nt++)
#pragma unroll
                for (int i = 0; i < 4; i++) c[mt][nt][i] = 0.f;
        nu_mma(shH, shW, 0, wm, wn, lane, c);

#pragma unroll
        for (int mt = 0; mt < 2; mt++) {
            int lrow0 = wm + mt * 16 + (lane >> 2);
#pragma unroll
            for (int nt = 0; nt < 4; nt++) {
                int col = wn + nt * 8 + 2 * (lane & 3);
                float cb0 = conv_b[col], cb1 = conv_b[col + 1];
#pragma unroll
                for (int hrow = 0; hrow < 2; hrow++) {
                    int lrow = lrow0 + hrow * 8;
                    int grow = bm + lrow;
                    float a0 = 0.f, a1 = 0.f;
                    if (grow < N) {
                        float id = g_invdeg[grow];
                        float2 ag = *(const float2*)(g_agg + (size_t)grow * DIMV + col);
                        a0 = ag.x * id; a1 = ag.y * id;
                    }
                    float m0 = fmaxf(c[mt][nt][2 * hrow]     + a0 + cb0, 0.f);
                    float m1 = fmaxf(c[mt][nt][2 * hrow + 1] + a1 + cb1, 0.f);
                    *(__half2*)(&shM[lrow][col]) = __floats2half2_rn(m0, m1);
                }
            }
        }
    }
    __syncthreads();

    // gate r
    float rfr[2][4][4];
#pragma unroll
    for (int mt = 0; mt < 2; mt++)
#pragma unroll
        for (int nt = 0; nt < 4; nt++)
#pragma unroll
            for (int i = 0; i < 4; i++) rfr[mt][nt][i] = 0.f;
    nu_mma(shM, shW, 64, wm, wn, lane, rfr);
    nu_mma(shH, shW, 256, wm, wn, lane, rfr);
#pragma unroll
    for (int mt = 0; mt < 2; mt++)
#pragma unroll
        for (int nt = 0; nt < 4; nt++) {
            int col = wn + nt * 8 + 2 * (lane & 3);
            float bb0 = b_ih[col] + b_hh[col];
            float bb1 = b_ih[col + 1] + b_hh[col + 1];
            rfr[mt][nt][0] = sigmoidf_(rfr[mt][nt][0] + bb0);
            rfr[mt][nt][1] = sigmoidf_(rfr[mt][nt][1] + bb1);
            rfr[mt][nt][2] = sigmoidf_(rfr[mt][nt][2] + bb0);
            rfr[mt][nt][3] = sigmoidf_(rfr[mt][nt][3] + bb1);
        }

    // gate n
    float nfr[2][4][4];
    {
        float cin[2][4][4], chn[2][4][4];
#pragma unroll
        for (int mt = 0; mt < 2; mt++)
#pragma unroll
            for (int nt = 0; nt < 4; nt++)
#pragma unroll
                for (int i = 0; i < 4; i++) { cin[mt][nt][i] = 0.f; chn[mt][nt][i] = 0.f; }
        nu_mma(shM, shW, 64 + 128, wm, wn, lane, cin);
        nu_mma(shH, shW, 256 + 128, wm, wn, lane, chn);
#pragma unroll
        for (int mt = 0; mt < 2; mt++)
#pragma unroll
            for (int nt = 0; nt < 4; nt++) {
                int col = wn + nt * 8 + 2 * (lane & 3);
                float bi0 = b_ih[128 + col], bi1 = b_ih[128 + col + 1];
                float bh0 = b_hh[128 + col], bh1 = b_hh[128 + col + 1];
                nfr[mt][nt][0] = tanhf(cin[mt][nt][0] + bi0 + rfr[mt][nt][0] * (chn[mt][nt][0] + bh0));
                nfr[mt][nt][1] = tanhf(cin[mt][nt][1] + bi1 + rfr[mt][nt][1] * (chn[mt][nt][1] + bh1));
                nfr[mt][nt][2] = tanhf(cin[mt][nt][2] + bi0 + rfr[mt][nt][2] * (chn[mt][nt][2] + bh0));
                nfr[mt][nt][3] = tanhf(cin[mt][nt][3] + bi1 + rfr[mt][nt][3] * (chn[mt][nt][3] + bh1));
            }
    }

    // gate z + h' = (1-z)*n + z*h_old
    {
        float cz[2][4][4];
#pragma unroll
        for (int mt = 0; mt < 2; mt++)
#pragma unroll
            for (int nt = 0; nt < 4; nt++)
#pragma unroll
                for (int i = 0; i < 4; i++) cz[mt][nt][i] = 0.f;
        nu_mma(shM, shW, 64 + 64, wm, wn, lane, cz);
        nu_mma(shH, shW, 256 + 64, wm, wn, lane, cz);
#pragma unroll
        for (int mt = 0; mt < 2; mt++) {
            int lrow0 = wm + mt * 16 + (lane >> 2);
#pragma unroll
            for (int nt = 0; nt < 4; nt++) {
                int col = wn + nt * 8 + 2 * (lane & 3);
                float bb0 = b_ih[64 + col] + b_hh[64 + col];
                float bb1 = b_ih[64 + col + 1] + b_hh[64 + col + 1];
#pragma unroll
                for (int hrow = 0; hrow < 2; hrow++) {
                    int grow = bm + lrow0 + hrow * 8;
                    if (grow >= N) continue;
                    float z0 = sigmoidf_(cz[mt][nt][2 * hrow]     + bb0);
                    float z1 = sigmoidf_(cz[mt][nt][2 * hrow + 1] + bb1);
                    float2 ho = *(const float2*)(g_h + (size_t)grow * DIMV + col);
                    float2 hn_;
                    hn_.x = (1.f - z0) * nfr[mt][nt][2 * hrow]     + z0 * ho.x;
                    hn_.y = (1.f - z1) * nfr[mt][nt][2 * hrow + 1] + z1 * ho.y;
                    *(float2*)(g_h + (size_t)grow * DIMV + col) = hn_;
                }
            }
        }
    }
}

// ---------------- bookkeeping ----------------
__global__ void count_kernel(const int* __restrict__ ei, const int* __restrict__ batch, int E, int N)
{
    int i = blockIdx.x * blockDim.x + threadIdx.x;
    if (i < E) atomicAdd(&g_degi[ei[E + i]], 1);
    if (i < N) atomicAdd(&g_cnt[batch[i]], 1);
}

__global__ void invdeg_kernel(int N)
{
    int i = blockIdx.x * blockDim.x + threadIdx.x;
    if (i < N) g_invdeg[i] = 1.f / fmaxf((float)g_degi[i], 1.f);
}

__global__ void scan_kernel()
{
    __shared__ int s[NG];
    int t = threadIdx.x;
    s[t] = g_cnt[t];
    __syncthreads();
    for (int off = 1; off < NG; off <<= 1) {
        int v = (t >= off) ? s[t - off] : 0;
        __syncthreads();
        s[t] += v;
        __syncthreads();
    }
    if (t == 0) g_gstart[0] = 0;
    g_gstart[t + 1] = s[t];
}

// ---------------- msg v2 (R7): uint4 loads, shfl reduce, 8 atomics/lane ----------------
__global__ void msg_kernel(const int* __restrict__ ei, int E)
{
    const int w    = threadIdx.x >> 5;
    const int lane = threadIdx.x & 31;
    const int e    = blockIdx.x * 8 + w;
    __shared__ float s_a[8][DIMV];

    if (e >= E) return;
    int src = ei[e];
    int dst = ei[E + e];
    s_a[w][lane]      = g_h[src * DIMV + lane];
    s_a[w][lane + 32] = g_h[src * DIMV + lane + 32];
    __syncwarp();

    const int o8 = lane & 7;
    const int ig = lane >> 3;

    float acc[8];
#pragma unroll
    for (int j = 0; j < 8; j++) acc[j] = 0.f;

    const uint4* __restrict__ wp = (const uint4*)(g_We_h + (size_t)e * WE_COLS);
#pragma unroll
    for (int step = 0; step < 16; step++) {
        int i = step * 4 + ig;
        uint4 v = wp[i * 8 + o8];
        float a = s_a[w][i];
        float2 f0 = __half22float2(*(__half2*)&v.x);
        float2 f1 = __half22float2(*(__half2*)&v.y);
        float2 f2 = __half22float2(*(__half2*)&v.z);
        float2 f3 = __half22float2(*(__half2*)&v.w);
        acc[0] = fmaf(a, f0.x, acc[0]); acc[1] = fmaf(a, f0.y, acc[1]);
        acc[2] = fmaf(a, f1.x, acc[2]); acc[3] = fmaf(a, f1.y, acc[3]);
        acc[4] = fmaf(a, f2.x, acc[4]); acc[5] = fmaf(a, f2.y, acc[5]);
        acc[6] = fmaf(a, f3.x, acc[6]); acc[7] = fmaf(a, f3.y, acc[7]);
    }

#pragma unroll
    for (int j = 0; j < 8; j++) {
        acc[j] += __shfl_xor_sync(0xffffffff, acc[j], 8);
        acc[j] += __shfl_xor_sync(0xffffffff, acc[j], 16);
    }

    if (lane < 8) {
        float* dp = g_agg + (size_t)dst * DIMV + lane * 8;
#pragma unroll
        for (int j = 0; j < 8; j++) atomicAdd(&dp[j], acc[j]);
    }
}

// ---------------- fused Set2Set (3 steps) + readout ----------------
__global__ void __launch_bounds__(128) set2set_kernel(
    const float* __restrict__ b_ih, const float* __restrict__ b_hh,
    const float* __restrict__ lin1_b, const float* __restrict__ lin2_w,
    const float* __restrict__ lin2_b, float* __restrict__ y)
{
    const int b = blockIdx.x, t = threadIdx.x;
    const int s = g_gstart[b], e_end = g_gstart[b + 1];

    __shared__ float qs[2 * DIMV];
    __shared__ float hsv[DIMV];
    __shared__ float csv[DIMV];
    __shared__ float gates[4 * DIMV];
    __shared__ float red[128];

    qs[t] = 0.f;
    if (t < 64) { hsv[t] = 0.f; csv[t] = 0.f; }
    __syncthreads();

    for (int step = 0; step < 3; step++) {
#pragma unroll
        for (int gsel = 0; gsel < 2; gsel++) {
            int gidx = t + gsel * 128;
            float acc = b_ih[gidx] + b_hh[gidx];
#pragma unroll 8
            for (int k = 0; k < 128; k++) acc += qs[k] * g_wihT[k * 256 + gidx];
#pragma unroll 8
            for (int k = 0; k < 64; k++)  acc += hsv[k] * g_whhT[k * 256 + gidx];
            gates[gidx] = acc;
        }
        __syncthreads();
        if (t < 64) {
            float i = sigmoidf_(gates[t]);
            float f = sigmoidf_(gates[64 + t]);
            float g = tanhf(gates[128 + t]);
            float o = sigmoidf_(gates[192 + t]);
            float c = f * csv[t] + i * g;
            csv[t] = c;
            hsv[t] = o * tanhf(c);
        }
        __syncthreads();

        float lmax = -1e30f;
        for (int n = s + t; n < e_end; n += 128) {
            const float* row = g_h + (size_t)n * DIMV;
            float acc = 0.f;
#pragma unroll 8
            for (int i = 0; i < DIMV; i++) acc += row[i] * hsv[i];
            g_ebuf[n] = acc;
            lmax = fmaxf(lmax, acc);
        }
        red[t] = lmax; __syncthreads();
        for (int st = 64; st > 0; st >>= 1) { if (t < st) red[t] = fmaxf(red[t], red[t + st]); __syncthreads(); }
        float gmax = red[0];
        __syncthreads();

        float lsum = 0.f;
        for (int n = s + t; n < e_end; n += 128) {
            float a = expf(g_ebuf[n] - gmax);
            g_ebuf[n] = a;
            lsum += a;
        }
        red[t] = lsum; __syncthreads();
        for (int st = 64; st > 0; st >>= 1) { if (t < st) red[t] += red[t + st]; __syncthreads(); }
        float S = red[0];
        __syncthreads();

        {
            int d = t & 63, half = t >> 6;
            float r = 0.f;
            for (int n = s + half; n < e_end; n += 2)
                r += g_ebuf[n] * g_h[(size_t)n * DIMV + d];
            red[t] = r;
        }
        __syncthreads();
        if (t < 64) {
            float rr = red[t] + red[t + 64];
            qs[t] = hsv[t];
            qs[64 + t] = (e_end > s) ? (rr / S) : 0.f;
        }
        __syncthreads();
    }

    if (t < 64) {
        float acc = lin1_b[t];
#pragma unroll 8
        for (int k = 0; k < 128; k++) acc += qs[k] * g_lin1T[k * 64 + t];
        float z = fmaxf(acc, 0.f);
        red[t] = z * lin2_w[t];
    }
    __syncthreads();
    for (int st = 32; st > 0; st >>= 1) { if (t < st) red[t] += red[t + st]; __syncthreads(); }
    if (t == 0) y[b] = red[0] + lin2_b[0];
}

// ======================================================================================
extern "C" void kernel_launch(void* const* d_in, const int* in_sizes, int n_in,
                              void* d_out, int out_size)
{
    const float* x        = (const float*)d_in[0];
    const int*   ei       = (const int*)  d_in[1];
    const float* ea       = (const float*)d_in[2];
    const int*   batch    = (const int*)  d_in[3];
    const float* lin0_w   = (const float*)d_in[4];
    const float* lin0_b   = (const float*)d_in[5];
    const float* nn1_w    = (const float*)d_in[6];
    const float* nn1_b    = (const float*)d_in[7];
    const float* nn2_w    = (const float*)d_in[8];
    const float* nn2_b    = (const float*)d_in[9];
    const float* root_w   = (const float*)d_in[10];
    const float* conv_b   = (const float*)d_in[11];
    const float* gru_w_ih = (const float*)d_in[12];
    const float* gru_w_hh = (const float*)d_in[13];
    const float* gru_b_ih = (const float*)d_in[14];
    const float* gru_b_hh = (const float*)d_in[15];
    const float* lstm_w_ih= (const float*)d_in[16];
    const float* lstm_w_hh= (const float*)d_in[17];
    const float* lstm_b_ih= (const float*)d_in[18];
    const float* lstm_b_hh= (const float*)d_in[19];
    const float* lin1_w   = (const float*)d_in[20];
    const float* lin1_b   = (const float*)d_in[21];
    const float* lin2_w   = (const float*)d_in[22];
    const float* lin2_b   = (const float*)d_in[23];
    float* y = (float*)d_out;

    const int N = NNODES, E = NEDGES;

    __half *We_h, *hedge_h, *nn2w_h;
    float *h, *agg;
    int *degi, *cnt;
    cudaGetSymbolAddress((void**)&We_h, g_We_h);
    cudaGetSymbolAddress((void**)&hedge_h, g_hedge_h);
    cudaGetSymbolAddress((void**)&nn2w_h, g_nn2w_h);
    cudaGetSymbolAddress((void**)&h, g_h);
    cudaGetSymbolAddress((void**)&agg, g_agg);
    cudaGetSymbolAddress((void**)&degi, g_degi);
    cudaGetSymbolAddress((void**)&cnt, g_cnt);

    const int we_smem = 2 * 128 * WG_LDK * (int)sizeof(__half);  // ~68 KB
    cudaFuncSetAttribute(we_gemm_kernel, cudaFuncAttributeMaxDynamicSharedMemorySize, we_smem);
    const int nu_smem = (448 + 128 + 128) * NU_LD * (int)sizeof(__half);
    cudaFuncSetAttribute(node_update_kernel, cudaFuncAttributeMaxDynamicSharedMemorySize, nu_smem);

    // kernel launches #1..#5, we_gemm is #6 for ncu -s 5 -c 1 (memsets not counted)
    prep_kernel<<<(WE_COLS * EHID + 255) / 256, 256>>>(nn2_w, root_w, gru_w_ih, gru_w_hh,
                                                       lstm_w_ih, lstm_w_hh, lin1_w);        // 1
    edge_mlp1_kernel<<<(E * EHID + 255) / 256, 256>>>(ea, nn1_w, nn1_b, E);                  // 2
    cudaMemsetAsync(degi, 0, N * sizeof(int));
    cudaMemsetAsync(cnt, 0, NG * sizeof(int));
    count_kernel<<<(E + 255) / 256, 256>>>(ei, batch, E, N);                                 // 3
    invdeg_kernel<<<(N + 255) / 256, 256>>>(N);                                              // 4
    scan_kernel<<<1, NG>>>();                                                                // 5
    {
        dim3 g(WE_COLS / 128, (E + 127) / 128);
        we_gemm_kernel<<<g, 128, we_smem>>>(hedge_h, nn2w_h, nn2_b, We_h, E);                // 6 (profiled)
    }

    // lin0: h = relu(x @ lin0^T + b)
    {
        dim3 g(DIMV / BN, (N + BM - 1) / BM);
        gemm_kernel<<<g, 256>>>(x, lin0_w, lin0_b, h, N, DIMV, NFEAT, 1);
    }

    // 3x NNConv + GRU
    for (int it = 0; it < 3; it++) {
        cudaMemsetAsync(agg, 0, (size_t)N * DIMV * sizeof(float));
        msg_kernel<<<(E + 7) / 8, 256>>>(ei, E);
        node_update_kernel<<<(N + 127) / 128, 256, nu_smem>>>(conv_b, gru_b_ih, gru_b_hh, N);
    }

    // fused Set2Set + readout
    set2set_kernel<<<NG, 128>>>(lstm_b_ih, lstm_b_hh, lin1_b, lin2_w, lin2_b, y);
}